// round 6
// baseline (speedup 1.0000x reference)
#include <cuda_runtime.h>
#include <cuda_bf16.h>

#define BATCH 64
#define NTOK  4096
#define CH    512
#define NUM_KEEP 2458            // ceil(4096 * 0.6)
#define TAIL (NTOK - NUM_KEEP)   // 1638
#define TAILP 2048               // padded per-batch stride for tail weights
#define C4   (CH / 4)            // 128 float4 per token row
#define PBV  (NUM_KEEP * C4)     // 314624 float4s of sel per batch
#define CHUNK 1024               // elements per sort1 CTA
#define NGROUP 32                // tail groups per batch
#define TAILB 8                  // tail CTAs per batch
#define COPYB 77                 // copy CTAs per batch (77*4096 >= PBV)
#define CONSUMERS (TAILB + COPYB)   // 85

// scratch (device globals: zero-initialized at module load; the flag/counter
// protocol below restores them to zero at the end of every launch, so graph
// replays are deterministic)
__device__ unsigned long long g_keys[BATCH * NTOK];   // 2 MB
__device__ int    g_sorted_idx[BATCH * NTOK];
__device__ float  g_tailw[BATCH * TAILP];    // UN-normalized exp weights
__device__ float  g_invsum[BATCH * 32];      // one cache line per batch
__device__ int    g_ready[BATCH];            // per-batch sort-done flag
__device__ int    g_cnt[BATCH];              // per-batch consumer countdown

// ---------------------------------------------------------------------------
// common helpers (descending bitonic on 64-bit packed keys)
// ---------------------------------------------------------------------------
__device__ __forceinline__ float decode_score(unsigned long long kk) {
    unsigned u = (unsigned)(kk >> 32);
    return (u & 0x80000000u) ? __uint_as_float(u & 0x7FFFFFFFu)
                             : __uint_as_float(~u);
}

__device__ __forceinline__ void cmpswap(unsigned long long& a,
                                        unsigned long long& c, bool desc) {
    bool sw = desc ? (a < c) : (a > c);
    if (sw) { unsigned long long t = a; a = c; c = t; }
}

// ---------------------------------------------------------------------------
// Kernel S1: 4 CTAs/batch, 512 threads, 2 elements/thread, chunk = 1024.
// Odd chunks fully inverted (ascending). shfl covers j<=32; smem quads j>=64.
// ---------------------------------------------------------------------------
__device__ __forceinline__ void shfl2(unsigned long long& r0,
                                      unsigned long long& r1,
                                      int base, int k, int j, bool flip) {
    int L = j >> 1;
    bool desc = (((base & k) == 0) != flip);
    bool keepmax = (((base & j) == 0) == desc);
    unsigned long long o0 = __shfl_xor_sync(0xFFFFFFFFu, r0, L);
    unsigned long long o1 = __shfl_xor_sync(0xFFFFFFFFu, r1, L);
    r0 = keepmax ? (r0 > o0 ? r0 : o0) : (r0 < o0 ? r0 : o0);
    r1 = keepmax ? (r1 > o1 ? r1 : o1) : (r1 < o1 ? r1 : o1);
}

__device__ __forceinline__ void wfin2(unsigned long long& r0,
                                      unsigned long long& r1,
                                      int base, int k, int jstart, bool flip) {
    for (int j = jstart; j >= 2; j >>= 1) shfl2(r0, r1, base, k, j, flip);
    bool d = (((base & k) == 0) != flip);
    cmpswap(r0, r1, d);
}

__global__ __launch_bounds__(512)
void ts_sort1_kernel(const float* __restrict__ ax,
                     const float* __restrict__ ay)
{
    __shared__ unsigned long long key[CHUNK];   // 8 KB

    const int chunk = blockIdx.x;        // 0..255
    const int b     = chunk >> 2;
    const int c     = chunk & 3;
    const bool flip = (c & 1);
    const int tid   = threadIdx.x;
    const int base  = tid << 1;          // element e0 in chunk
    const int gbase = (c << 10) + base;  // token index within batch

    unsigned long long r0, r1;
    {
        float2 x = *(const float2*)(ax + b * NTOK + gbase);
        float2 y = *(const float2*)(ay + b * NTOK + gbase);
        float s0 = x.x + y.x, s1 = x.y + y.y;
        unsigned u0 = __float_as_uint(s0);
        u0 = (u0 & 0x80000000u) ? ~u0 : (u0 | 0x80000000u);
        unsigned u1 = __float_as_uint(s1);
        u1 = (u1 & 0x80000000u) ? ~u1 : (u1 | 0x80000000u);
        r0 = ((unsigned long long)u0 << 32) | (unsigned)(~gbase);
        r1 = ((unsigned long long)u1 << 32) | (unsigned)(~(gbase + 1));
    }

    // k = 2..64 : registers + shuffles only
    cmpswap(r0, r1, ((base & 2) == 0) != flip);
    for (int k = 4; k <= 64; k <<= 1)
        wfin2(r0, r1, base, k, k >> 1, flip);

    // k = 128..1024 : smem quad passes (levels j,j/2 together), warp finish
    for (int k = 128; k <= CHUNK; k <<= 1) {
        *(ulonglong2*)&key[base] = make_ulonglong2(r0, r1);
        __syncthreads();
        int j = k >> 1;
        while (j >= 64) {
            int j2 = j >> 1;
            if (tid < 256) {
                int q = tid;
                int i = ((q & ~(j2 - 1)) << 2) | (q & (j2 - 1));
                bool d = (((i & k) == 0) != flip);
                unsigned long long a0 = key[i];
                unsigned long long a1 = key[i + j2];
                unsigned long long a2 = key[i + 2 * j2];
                unsigned long long a3 = key[i + 3 * j2];
                cmpswap(a0, a2, d);
                cmpswap(a1, a3, d);
                cmpswap(a0, a1, d);
                cmpswap(a2, a3, d);
                key[i]          = a0;
                key[i + j2]     = a1;
                key[i + 2 * j2] = a2;
                key[i + 3 * j2] = a3;
            }
            __syncthreads();
            j >>= 2;
        }
        ulonglong2 p = *(ulonglong2*)&key[base];
        r0 = p.x; r1 = p.y;
        wfin2(r0, r1, base, k, j, flip);   // j is 32 or 16 here
    }

    *(ulonglong2*)(g_keys + b * NTOK + gbase) = make_ulonglong2(r0, r1);
}

// ---------------------------------------------------------------------------
// MEGA kernel: bids 0..63 = sort2 (finish k=2048,4096 + epilogue + set flag),
// remaining bids = per-batch consumers (8 tail CTAs + 77 copy CTAs) that
// spin-wait on their batch flag. Flags/counters self-reset (85th consumer).
// ---------------------------------------------------------------------------
__device__ __forceinline__ void shfl_stage8(unsigned long long r[8],
                                            int base, int k, int j) {
    int L = j >> 3;
    bool desc = ((base & k) == 0);
    bool keepmax = (((base & j) == 0) == desc);
    #pragma unroll
    for (int m = 0; m < 8; ++m) {
        unsigned long long o = __shfl_xor_sync(0xFFFFFFFFu, r[m], L);
        r[m] = keepmax ? (r[m] > o ? r[m] : o) : (r[m] < o ? r[m] : o);
    }
}

__global__ __launch_bounds__(512)
void ts_mega_kernel(const float* __restrict__ tokens,
                    float* __restrict__ sel,
                    float* __restrict__ extra,
                    float* __restrict__ mask_out)
{
    __shared__ unsigned long long key[NTOK];   // 32 KB (used by sort2 CTAs)

    const int tid = threadIdx.x;

    if (blockIdx.x < BATCH) {
        // ================= sort2: finish k = 2048, 4096 =================
        const int b    = blockIdx.x;
        const int base = tid << 3;      // 8 elements per thread

        if (tid < CH) extra[b * CH + tid] = 0.0f;   // zero extra slice

        unsigned long long r[8];
        {
            const ulonglong2* src = (const ulonglong2*)(g_keys + b * NTOK + base);
            #pragma unroll
            for (int m = 0; m < 4; ++m) {
                ulonglong2 p = src[m];
                r[2 * m] = p.x; r[2 * m + 1] = p.y;
            }
        }

        for (int k = 2048; k <= NTOK; k <<= 1) {
            #pragma unroll
            for (int m = 0; m < 4; ++m)
                *(ulonglong2*)&key[base + 2 * m] =
                    make_ulonglong2(r[2 * m], r[2 * m + 1]);
            __syncthreads();
            int j = k >> 1;
            while (j >= 256) {
                int j2 = j >> 1;
                #pragma unroll
                for (int h = 0; h < 2; ++h) {
                    int q = tid + (h << 9);
                    int i = ((q & ~(j2 - 1)) << 2) | (q & (j2 - 1));
                    bool d = ((i & k) == 0);
                    unsigned long long a0 = key[i];
                    unsigned long long a1 = key[i + j2];
                    unsigned long long a2 = key[i + 2 * j2];
                    unsigned long long a3 = key[i + 3 * j2];
                    cmpswap(a0, a2, d);
                    cmpswap(a1, a3, d);
                    cmpswap(a0, a1, d);
                    cmpswap(a2, a3, d);
                    key[i]          = a0;
                    key[i + j2]     = a1;
                    key[i + 2 * j2] = a2;
                    key[i + 3 * j2] = a3;
                }
                __syncthreads();
                j >>= 2;
            }
            #pragma unroll
            for (int m = 0; m < 4; ++m) {
                ulonglong2 p = *(ulonglong2*)&key[base + 2 * m];
                r[2 * m] = p.x; r[2 * m + 1] = p.y;
            }
            // warp finish: j (128 or 64) down to 8 via shfl, then in-reg
            for (int j2 = j; j2 >= 8; j2 >>= 1) shfl_stage8(r, base, k, j2);
            bool d = ((base & k) == 0);
            cmpswap(r[0], r[4], d); cmpswap(r[1], r[5], d);
            cmpswap(r[2], r[6], d); cmpswap(r[3], r[7], d);
            cmpswap(r[0], r[2], d); cmpswap(r[1], r[3], d);
            cmpswap(r[4], r[6], d); cmpswap(r[5], r[7], d);
            cmpswap(r[0], r[1], d); cmpswap(r[2], r[3], d);
            cmpswap(r[4], r[5], d); cmpswap(r[6], r[7], d);
        }

        // ======================= epilogue =======================
        __shared__ float red[17];
        if (base <= NUM_KEEP && NUM_KEEP < base + 8)
            red[16] = decode_score(r[NUM_KEEP - base]);
        __syncthreads();
        const float mx = red[16];

        float local_sum = 0.f;
        int idx8[8];
        #pragma unroll
        for (int m = 0; m < 8; ++m) {
            int rank = base + m;
            int idx = (int)(~(unsigned)r[m]);
            idx8[m] = idx;
            mask_out[b * NTOK + idx] = (rank < NUM_KEEP) ? 1.0f : 0.0f;
            if (rank >= NUM_KEEP) {
                float e = expf(decode_score(r[m]) - mx);
                g_tailw[b * TAILP + (rank - NUM_KEEP)] = e;
                local_sum += e;
            }
        }
        *(int4*)(g_sorted_idx + b * NTOK + base) =
            make_int4(idx8[0], idx8[1], idx8[2], idx8[3]);
        *(int4*)(g_sorted_idx + b * NTOK + base + 4) =
            make_int4(idx8[4], idx8[5], idx8[6], idx8[7]);

        for (int off = 16; off > 0; off >>= 1)
            local_sum += __shfl_down_sync(0xFFFFFFFFu, local_sum, off);
        if ((tid & 31) == 0) red[tid >> 5] = local_sum;
        __syncthreads();
        if (tid < 32) {
            float v = (tid < 16) ? red[tid] : 0.f;
            for (int off = 8; off > 0; off >>= 1)
                v += __shfl_down_sync(0xFFFFFFFFu, v, off);
            if (tid == 0) g_invsum[b * 32] = 1.0f / v;
        }
        __syncthreads();
        if (tid == 0) {
            __threadfence();                      // publish all batch-b data
            atomicExch(&g_ready[b], 1);
        }
        return;
    }

    // ======================= consumers =======================
    const int u = blockIdx.x - BATCH;
    const int b = u / CONSUMERS;
    const int s = u - b * CONSUMERS;

    // spin until batch b's sort is published
    if (tid == 0) {
        while (atomicAdd(&g_ready[b], 0) == 0) __nanosleep(256);
    }
    __syncthreads();

    if (s < TAILB) {
        // ---- tail: extra += invsum * sum_r w_r * tokens[b, nonkeep_r, :] ----
        const int g    = (s << 2) | (tid >> 7);    // 0..31
        const int lane = tid & 127;

        const int* __restrict__ sidx = g_sorted_idx + b * NTOK + NUM_KEEP;
        const float* __restrict__ w  = g_tailw + b * TAILP;
        const float4* __restrict__ tok4 = (const float4*)tokens
                                          + ((long long)b * NTOK << 7);

        float4 acc = make_float4(0.f, 0.f, 0.f, 0.f);
        int r = g;
        for (; r + NGROUP < TAIL; r += 2 * NGROUP) {
            int   i0 = sidx[r],    i1 = sidx[r + NGROUP];
            float w0 = w[r],       w1 = w[r + NGROUP];
            float4 v0 = __ldcs(&tok4[((long long)i0 << 7) + lane]);
            float4 v1 = __ldcs(&tok4[((long long)i1 << 7) + lane]);
            acc.x += w0 * v0.x + w1 * v1.x;
            acc.y += w0 * v0.y + w1 * v1.y;
            acc.z += w0 * v0.z + w1 * v1.z;
            acc.w += w0 * v0.w + w1 * v1.w;
        }
        if (r < TAIL) {
            int i0 = sidx[r];
            float w0 = w[r];
            float4 v0 = __ldcs(&tok4[((long long)i0 << 7) + lane]);
            acc.x += w0 * v0.x; acc.y += w0 * v0.y;
            acc.z += w0 * v0.z; acc.w += w0 * v0.w;
        }
        float sc = g_invsum[b * 32];
        float* dst = extra + b * CH + (lane << 2);
        atomicAdd(dst + 0, acc.x * sc);
        atomicAdd(dst + 1, acc.y * sc);
        atomicAdd(dst + 2, acc.z * sc);
        atomicAdd(dst + 3, acc.w * sc);
    } else {
        // ---- copy: 4096 float4s per CTA within batch b, guarded ----
        const int c  = s - TAILB;              // 0..76
        const int v0 = (c << 12) + tid;

        long long srcoff[8];
        bool ok[8];
        #pragma unroll
        for (int i = 0; i < 8; ++i) {
            int v = v0 + (i << 9);
            ok[i] = (v < PBV);
            int row  = ok[i] ? (v >> 7) : 0;
            int lane = v & 127;
            int idx = __ldg(&g_sorted_idx[b * NTOK + row]);
            srcoff[i] = (((long long)b * NTOK + idx) << 7) + lane;
        }
        float4 val[8];
        #pragma unroll
        for (int i = 0; i < 8; ++i)
            if (ok[i]) val[i] = __ldcs(((const float4*)tokens) + srcoff[i]);
        #pragma unroll
        for (int i = 0; i < 8; ++i)
            if (ok[i]) __stcs(((float4*)sel) + (long long)b * PBV + v0 + (i << 9),
                              val[i]);
    }

    // completion count; the 85th consumer resets the flag + counter so the
    // device state returns to zero for the next graph replay
    __syncthreads();
    if (tid == 0) {
        int old = atomicAdd(&g_cnt[b], 1);
        if (old == CONSUMERS - 1) {
            atomicExch(&g_cnt[b], 0);
            atomicExch(&g_ready[b], 0);
        }
    }
}

// ---------------------------------------------------------------------------
extern "C" void kernel_launch(void* const* d_in, const int* in_sizes, int n_in,
                              void* d_out, int out_size)
{
    const float* tokens = (const float*)d_in[0];
    const float* ax     = (const float*)d_in[1];
    const float* ay     = (const float*)d_in[2];

    float* out = (float*)d_out;
    float* sel   = out;                                      // B*NUM_KEEP*C
    float* extra = out + (long long)BATCH * NUM_KEEP * CH;   // B*C
    float* mask  = extra + (long long)BATCH * CH;            // B*N

    ts_sort1_kernel<<<BATCH * 4, 512>>>(ax, ay);
    ts_mega_kernel<<<BATCH + BATCH * CONSUMERS, 512>>>(tokens, sel, extra, mask);
}

// round 7
// speedup vs baseline: 1.1404x; 1.1404x over previous
#include <cuda_runtime.h>
#include <cuda_bf16.h>

#define BATCH 64
#define NTOK  4096
#define CH    512
#define NUM_KEEP 2458            // ceil(4096 * 0.6)
#define TAIL (NTOK - NUM_KEEP)   // 1638
#define C4   (CH / 4)            // 128 float4 per token row
#define NGROUP 32                // tail groups per batch
#define TAIL_CTAS (BATCH * 8)    // 512 CTAs, 4 groups of 128 lanes each
#define COPY_CTAS 4916           // TOTAL_V / 4096 float4s per CTA, exact
#define CHUNK 1024               // elements per sort1 CTA

// scratch (device globals: no allocation allowed)
__device__ unsigned long long g_keys[BATCH * NTOK];   // 2 MB
__device__ int    g_sorted_idx[BATCH * NTOK];
__device__ float  g_tailw[BATCH * TAIL];     // UN-normalized exp weights
__device__ float  g_invsum[BATCH];

// ---------------------------------------------------------------------------
// common helpers (bitonic on 64-bit packed keys; flip inverts comparators)
// ---------------------------------------------------------------------------
__device__ __forceinline__ float decode_score(unsigned long long kk) {
    unsigned u = (unsigned)(kk >> 32);
    return (u & 0x80000000u) ? __uint_as_float(u & 0x7FFFFFFFu)
                             : __uint_as_float(~u);
}

__device__ __forceinline__ void cmpswap(unsigned long long& a,
                                        unsigned long long& c, bool desc) {
    bool sw = desc ? (a < c) : (a > c);
    if (sw) { unsigned long long t = a; a = c; c = t; }
}

// ---------------------------------------------------------------------------
// Kernel S1: 4 CTAs/batch, 512 threads, 2 elements/thread, chunk = 1024.
// Odd chunks fully inverted (ascending). shfl covers j<=32; smem quads j>=64.
// ---------------------------------------------------------------------------
__device__ __forceinline__ void shfl2(unsigned long long& r0,
                                      unsigned long long& r1,
                                      int base, int k, int j, bool flip) {
    int L = j >> 1;
    bool desc = (((base & k) == 0) != flip);
    bool keepmax = (((base & j) == 0) == desc);
    unsigned long long o0 = __shfl_xor_sync(0xFFFFFFFFu, r0, L);
    unsigned long long o1 = __shfl_xor_sync(0xFFFFFFFFu, r1, L);
    r0 = keepmax ? (r0 > o0 ? r0 : o0) : (r0 < o0 ? r0 : o0);
    r1 = keepmax ? (r1 > o1 ? r1 : o1) : (r1 < o1 ? r1 : o1);
}

__device__ __forceinline__ void wfin2(unsigned long long& r0,
                                      unsigned long long& r1,
                                      int base, int k, int jstart, bool flip) {
    for (int j = jstart; j >= 2; j >>= 1) shfl2(r0, r1, base, k, j, flip);
    bool d = (((base & k) == 0) != flip);
    cmpswap(r0, r1, d);
}

__global__ __launch_bounds__(512)
void ts_sort1_kernel(const float* __restrict__ ax,
                     const float* __restrict__ ay)
{
    __shared__ unsigned long long key[CHUNK];   // 8 KB

    const int chunk = blockIdx.x;        // 0..255
    const int b     = chunk >> 2;
    const int c     = chunk & 3;
    const bool flip = (c & 1);
    const int tid   = threadIdx.x;
    const int base  = tid << 1;          // element e0 in chunk
    const int gbase = (c << 10) + base;  // token index within batch

    unsigned long long r0, r1;
    {
        float2 x = *(const float2*)(ax + b * NTOK + gbase);
        float2 y = *(const float2*)(ay + b * NTOK + gbase);
        float s0 = x.x + y.x, s1 = x.y + y.y;
        unsigned u0 = __float_as_uint(s0);
        u0 = (u0 & 0x80000000u) ? ~u0 : (u0 | 0x80000000u);
        unsigned u1 = __float_as_uint(s1);
        u1 = (u1 & 0x80000000u) ? ~u1 : (u1 | 0x80000000u);
        r0 = ((unsigned long long)u0 << 32) | (unsigned)(~gbase);
        r1 = ((unsigned long long)u1 << 32) | (unsigned)(~(gbase + 1));
    }

    // k = 2..64 : registers + shuffles only
    cmpswap(r0, r1, ((base & 2) == 0) != flip);
    for (int k = 4; k <= 64; k <<= 1)
        wfin2(r0, r1, base, k, k >> 1, flip);

    // k = 128..1024 : smem quad passes (levels j,j/2 together), warp finish
    for (int k = 128; k <= CHUNK; k <<= 1) {
        *(ulonglong2*)&key[base] = make_ulonglong2(r0, r1);
        __syncthreads();
        int j = k >> 1;
        while (j >= 64) {
            int j2 = j >> 1;
            if (tid < 256) {
                int q = tid;
                int i = ((q & ~(j2 - 1)) << 2) | (q & (j2 - 1));
                bool d = (((i & k) == 0) != flip);
                unsigned long long a0 = key[i];
                unsigned long long a1 = key[i + j2];
                unsigned long long a2 = key[i + 2 * j2];
                unsigned long long a3 = key[i + 3 * j2];
                cmpswap(a0, a2, d);
                cmpswap(a1, a3, d);
                cmpswap(a0, a1, d);
                cmpswap(a2, a3, d);
                key[i]          = a0;
                key[i + j2]     = a1;
                key[i + 2 * j2] = a2;
                key[i + 3 * j2] = a3;
            }
            __syncthreads();
            j >>= 2;
        }
        ulonglong2 p = *(ulonglong2*)&key[base];
        r0 = p.x; r1 = p.y;
        wfin2(r0, r1, base, k, j, flip);   // j is 32 or 16 here
    }

    *(ulonglong2*)(g_keys + b * NTOK + gbase) = make_ulonglong2(r0, r1);
}

// ---------------------------------------------------------------------------
// Kernel S2: one CTA per batch finishes stages k = 2048, 4096, then the
// epilogue (mask, sorted idx, tail exp weights, invsum, zero extra).
// (identical to R5's proven version)
// ---------------------------------------------------------------------------
__device__ __forceinline__ void shfl_stage4(unsigned long long r[4],
                                            int base, int k, int j) {
    int L = j >> 2;
    bool lower = ((base & j) == 0);
    bool desc  = ((base & k) == 0);
    bool keepmax = (lower == desc);
    #pragma unroll
    for (int m = 0; m < 4; ++m) {
        unsigned long long o = __shfl_xor_sync(0xFFFFFFFFu, r[m], L);
        r[m] = keepmax ? (r[m] > o ? r[m] : o) : (r[m] < o ? r[m] : o);
    }
}

__device__ __forceinline__ void warp_pass4(unsigned long long r[4],
                                           int base, int k, int jmax) {
    for (int j = jmax; j >= 4; j >>= 1) shfl_stage4(r, base, k, j);
    bool desc = ((base & k) == 0);
    cmpswap(r[0], r[2], desc);
    cmpswap(r[1], r[3], desc);
    cmpswap(r[0], r[1], desc);
    cmpswap(r[2], r[3], desc);
}

__global__ __launch_bounds__(1024)
void ts_sort2_kernel(float* __restrict__ mask_out,
                     float* __restrict__ extra)
{
    __shared__ unsigned long long key[NTOK];   // 32 KB
    __shared__ float red[33];

    const int b    = blockIdx.x;
    const int tid  = threadIdx.x;
    const int base = ((tid >> 5) << 7) | ((tid & 31) << 2);   // 0..4095

    if (tid < CH) extra[b * CH + tid] = 0.0f;

    unsigned long long r[4];
    {
        const unsigned long long* src = g_keys + b * NTOK + base;
        ulonglong2 p0 = ((const ulonglong2*)src)[0];
        ulonglong2 p1 = ((const ulonglong2*)src)[1];
        r[0] = p0.x; r[1] = p0.y; r[2] = p1.x; r[3] = p1.y;
    }

    // stages k = 2048, 4096 : paired smem levels + warp finish
    for (int k = 2048; k <= NTOK; k <<= 1) {
        #pragma unroll
        for (int m = 0; m < 4; ++m) key[base + m] = r[m];
        __syncthreads();
        int j = k >> 1;
        while (j >= 128) {
            int j2 = j >> 1;
            int i  = (tid << 2) - 3 * (tid & (j2 - 1));
            bool d = ((i & k) == 0);
            unsigned long long a0 = key[i];
            unsigned long long a1 = key[i + j2];
            unsigned long long a2 = key[i + 2 * j2];
            unsigned long long a3 = key[i + 3 * j2];
            cmpswap(a0, a2, d);
            cmpswap(a1, a3, d);
            cmpswap(a0, a1, d);
            cmpswap(a2, a3, d);
            key[i]          = a0;
            key[i + j2]     = a1;
            key[i + 2 * j2] = a2;
            key[i + 3 * j2] = a3;
            __syncthreads();
            j >>= 2;
        }
        #pragma unroll
        for (int m = 0; m < 4; ++m) r[m] = key[base + m];
        warp_pass4(r, base, k, j);
    }

    // softmax max = score at rank NUM_KEEP
    if (base <= NUM_KEEP && NUM_KEEP < base + 4)
        red[32] = decode_score(r[NUM_KEEP - base]);
    __syncthreads();
    const float mx = red[32];

    float local_sum = 0.f;
    int idx4[4];
    #pragma unroll
    for (int m = 0; m < 4; ++m) {
        int rank = base + m;
        int idx = (int)(~(unsigned)r[m]);
        idx4[m] = idx;
        mask_out[b * NTOK + idx] = (rank < NUM_KEEP) ? 1.0f : 0.0f;
        if (rank >= NUM_KEEP) {
            float e = expf(decode_score(r[m]) - mx);
            g_tailw[b * TAIL + (rank - NUM_KEEP)] = e;
            local_sum += e;
        }
    }
    *(int4*)(g_sorted_idx + b * NTOK + base) =
        make_int4(idx4[0], idx4[1], idx4[2], idx4[3]);

    for (int off = 16; off > 0; off >>= 1)
        local_sum += __shfl_down_sync(0xFFFFFFFFu, local_sum, off);
    if ((tid & 31) == 0) red[tid >> 5] = local_sum;
    __syncthreads();
    if (tid < 32) {
        float v = red[tid];
        for (int off = 16; off > 0; off >>= 1)
            v += __shfl_down_sync(0xFFFFFFFFu, v, off);
        if (tid == 0) g_invsum[b] = 1.0f / v;
    }
}

// ---------------------------------------------------------------------------
// Kernel 3 (fused): tail accumulation + gather copy, streaming cache hints.
// (identical to R5's proven roofline version)
// ---------------------------------------------------------------------------
__global__ __launch_bounds__(512)
void ts_main_kernel(const float* __restrict__ tokens,
                    float* __restrict__ sel,
                    float* __restrict__ extra)
{
    if (blockIdx.x < TAIL_CTAS) {
        const int b    = blockIdx.x >> 3;
        const int g    = ((blockIdx.x & 7) << 2) | (threadIdx.x >> 7); // 0..31
        const int lane = threadIdx.x & 127;

        const int* __restrict__ sidx = g_sorted_idx + b * NTOK + NUM_KEEP;
        const float* __restrict__ w  = g_tailw + b * TAIL;
        const float4* __restrict__ tok4 = (const float4*)tokens
                                          + ((long long)b * NTOK << 7);

        float4 acc = make_float4(0.f, 0.f, 0.f, 0.f);
        int r = g;
        for (; r + NGROUP < TAIL; r += 2 * NGROUP) {
            int   i0 = sidx[r],    i1 = sidx[r + NGROUP];
            float w0 = w[r],       w1 = w[r + NGROUP];
            float4 v0 = __ldcs(&tok4[((long long)i0 << 7) + lane]);
            float4 v1 = __ldcs(&tok4[((long long)i1 << 7) + lane]);
            acc.x += w0 * v0.x + w1 * v1.x;
            acc.y += w0 * v0.y + w1 * v1.y;
            acc.z += w0 * v0.z + w1 * v1.z;
            acc.w += w0 * v0.w + w1 * v1.w;
        }
        if (r < TAIL) {
            int i0 = sidx[r];
            float w0 = w[r];
            float4 v0 = __ldcs(&tok4[((long long)i0 << 7) + lane]);
            acc.x += w0 * v0.x; acc.y += w0 * v0.y;
            acc.z += w0 * v0.z; acc.w += w0 * v0.w;
        }
        float s = g_invsum[b];
        float* dst = extra + b * CH + (lane << 2);
        atomicAdd(dst + 0, acc.x * s);
        atomicAdd(dst + 1, acc.y * s);
        atomicAdd(dst + 2, acc.z * s);
        atomicAdd(dst + 3, acc.w * s);
    } else {
        const int cta = blockIdx.x - TAIL_CTAS;
        const int v0  = (cta << 12) + threadIdx.x;

        long long srcoff[8];
        #pragma unroll
        for (int i = 0; i < 8; ++i) {
            int v = v0 + (i << 9);
            int row  = v >> 7;                 // b*NUM_KEEP + r
            int lane = v & 127;
            int b = row / NUM_KEEP;
            int r = row - b * NUM_KEEP;
            int idx = __ldg(&g_sorted_idx[b * NTOK + r]);
            srcoff[i] = (((long long)b * NTOK + idx) << 7) + lane;
        }
        float4 val[8];
        #pragma unroll
        for (int i = 0; i < 8; ++i)
            val[i] = __ldcs(((const float4*)tokens) + srcoff[i]);
        #pragma unroll
        for (int i = 0; i < 8; ++i)
            __stcs(((float4*)sel) + v0 + (i << 9), val[i]);
    }
}

// ---------------------------------------------------------------------------
extern "C" void kernel_launch(void* const* d_in, const int* in_sizes, int n_in,
                              void* d_out, int out_size)
{
    const float* tokens = (const float*)d_in[0];
    const float* ax     = (const float*)d_in[1];
    const float* ay     = (const float*)d_in[2];

    float* out = (float*)d_out;
    float* sel   = out;                                      // B*NUM_KEEP*C
    float* extra = out + (long long)BATCH * NUM_KEEP * CH;   // B*C
    float* mask  = extra + (long long)BATCH * CH;            // B*N

    ts_sort1_kernel<<<BATCH * 4, 512>>>(ax, ay);
    ts_sort2_kernel<<<BATCH, 1024>>>(mask, extra);
    ts_main_kernel<<<TAIL_CTAS + COPY_CTAS, 512>>>(tokens, sel, extra);
}